// round 11
// baseline (speedup 1.0000x reference)
#include <cuda_runtime.h>
#include <cuda_fp16.h>
#include <math.h>
#include <stdint.h>

#define BATCH 8
#define NSEQ  2048
#define HDIM  1024
#define FDIM  4096
#define MTOT  (BATCH * NSEQ)

typedef __half  f16;
typedef __half2 f162;

// ---------------- scratch (__device__ globals; allocation-free) ----------------
static __device__ __align__(16) f16   g_lnh[(size_t)MTOT * HDIM];
static __device__ __align__(16) f16   g_qh [(size_t)MTOT * HDIM];
static __device__ __align__(16) f16   g_kh [(size_t)MTOT * HDIM];
static __device__ __align__(16) f16   g_vh [(size_t)MTOT * HDIM];
static __device__ __align__(16) f16   g_vth[(size_t)MTOT * HDIM];
static __device__ __align__(16) float g_s  [(size_t)BATCH * NSEQ * NSEQ];
static __device__ __align__(16) f16   g_ph [(size_t)BATCH * NSEQ * NSEQ];
static __device__ __align__(16) float g_x1 [(size_t)MTOT * HDIM];
static __device__ __align__(16) f16   g_hh [(size_t)MTOT * FDIM];
static __device__ __align__(16) f16   g_wqh[(size_t)HDIM * HDIM];
static __device__ __align__(16) f16   g_wkh[(size_t)HDIM * HDIM];
static __device__ __align__(16) f16   g_wvh[(size_t)HDIM * HDIM];
static __device__ __align__(16) f16   g_w1h[(size_t)FDIM * HDIM];
static __device__ __align__(16) f16   g_w2h[(size_t)HDIM * FDIM];

// ---------------- helpers ----------------
__device__ __forceinline__ uint32_t smem_u32(const void* p) {
    uint32_t a;
    asm("{ .reg .u64 t; cvta.to.shared.u64 t, %1; cvt.u32.u64 %0, t; }" : "=r"(a) : "l"(p));
    return a;
}
__device__ __forceinline__ void cpa16(uint32_t dst, const f16* src) {
    asm volatile("cp.async.cg.shared.global [%0], [%1], 16;" :: "r"(dst), "l"(src));
}
__device__ __forceinline__ void cp_commit() { asm volatile("cp.async.commit_group;" ::: "memory"); }
__device__ __forceinline__ void ldm4(uint32_t* a, uint32_t addr) {
    asm volatile("ldmatrix.sync.aligned.m8n8.x4.shared.b16 {%0,%1,%2,%3}, [%4];"
                 : "=r"(a[0]), "=r"(a[1]), "=r"(a[2]), "=r"(a[3]) : "r"(addr));
}
__device__ __forceinline__ void mma16816(float* d, const uint32_t* a, const uint32_t* b) {
    asm volatile(
        "mma.sync.aligned.m16n8k16.row.col.f32.f16.f16.f32 "
        "{%0,%1,%2,%3}, {%4,%5,%6,%7}, {%8,%9}, {%0,%1,%2,%3};"
        : "+f"(d[0]), "+f"(d[1]), "+f"(d[2]), "+f"(d[3])
        : "r"(a[0]), "r"(a[1]), "r"(a[2]), "r"(a[3]), "r"(b[0]), "r"(b[1]));
}
__device__ __forceinline__ float gelu_exact(float x) {
    return 0.5f * x * (1.0f + erff(x * 0.70710678118654752440f));
}

// ---------------------------------------------------------------------------
// fp16 mma.sync GEMM: C = alpha*(A @ B^T) (+epilogue)
// A:[M,K], B:[N,K] fp16, K-major. Block tile 128(m) x 256(n), kchunk 32,
// 512 threads (16 warps, 2m x 8n, warp tile 64x32), fp32 accum,
// 3-stage cp.async pipeline, 1 CTA/SM.
// smem: 3 stages x (A 128x80 + B 256x80) = 92160 B.
// EPI: 0 Cf=alpha*acc | 2 Cf=acc+res | 3 Ch=gelu(acc+bias) |
//      4 Cf=acc+bias+res | 5 Ch=acc
// ---------------------------------------------------------------------------
#define PA      10240            /* A plane: 128 rows x 80B */
#define PB      20480            /* B plane: 256 rows x 80B */
#define STAGE   (PA + PB)
#define MM_SMEM (3 * STAGE)

template<int EPI>
__global__ void __launch_bounds__(512, 1) mm_kernel(
    const f16* __restrict__ Ah,
    const f16* __restrict__ Bh,
    int K, long long strA, long long strB, long long strC,
    int ldc, float alpha,
    float* __restrict__ Cf, const float* __restrict__ bias,
    const float* __restrict__ res, long long strRes,
    f16* __restrict__ Ch)
{
    extern __shared__ __align__(16) char smem[];
    const uint32_t su = smem_u32(smem);
    const int tid  = threadIdx.x;
    const int lane = tid & 31;
    const int warp = tid >> 5;
    const int bz   = blockIdx.z;
    const int bm   = blockIdx.y * 128;
    const int bn   = blockIdx.x * 256;

    Ah += (size_t)strA * bz;
    Bh += (size_t)strB * bz;

    // A loader: 512 x 16B loads, 1/thread. row = tid>>2, 16B-chunk = tid&3
    const int rA = tid >> 2, cA = tid & 3;
    const uint32_t dA = (uint32_t)(rA * 80 + cA * 16);
    const size_t  gA = (size_t)(bm + rA) * K + cA * 8;
    // B loader: 1024 x 16B loads, 2/thread. idx in {tid, tid+512}
    const int rB0 = tid >> 2,          cB0 = tid & 3;
    const int rB1 = (tid + 512) >> 2,  cB1 = tid & 3;
    const uint32_t dB0 = (uint32_t)(rB0 * 80 + cB0 * 16);
    const uint32_t dB1 = (uint32_t)(rB1 * 80 + cB1 * 16);
    const size_t  gB0 = (size_t)(bn + rB0) * K + cB0 * 8;
    const size_t  gB1 = (size_t)(bn + rB1) * K + cB1 * 8;

    const int nch = K >> 5;

    // warp tile: 2 (m) x 8 (n)
    const int wm = (warp & 1) * 64;
    const int wn = (warp >> 1) * 32;

    float acc[4][4][4];
    #pragma unroll
    for (int i = 0; i < 4; i++)
        #pragma unroll
        for (int j = 0; j < 4; j++)
            #pragma unroll
            for (int r = 0; r < 4; r++) acc[i][j][r] = 0.0f;

    // A ldmatrix lane address components
    const int arow = lane & 15;
    const int acol = (lane >> 4) * 16;               // bytes
    // B ldmatrix lane address components
    const int bg   = lane >> 3;                      // 0..3 (matrix group)
    const int br   = lane & 7;
    const uint32_t boff = (uint32_t)(((bg >> 1) * 8 + br) * 80 + (bg & 1) * 16);

    // prologue: stages for chunks 0, 1
    #pragma unroll
    for (int p = 0; p < 2; p++) {
        const uint32_t b = su + p * STAGE;
        const size_t k0 = (size_t)p << 5;
        cpa16(b + dA,            Ah + gA  + k0);
        cpa16(b + PA + dB0,      Bh + gB0 + k0);
        cpa16(b + PA + dB1,      Bh + gB1 + k0);
        cp_commit();
    }

    int buf = 0;
    for (int c = 0; c < nch; c++) {
        if (c + 1 < nch) asm volatile("cp.async.wait_group 1;" ::: "memory");
        else             asm volatile("cp.async.wait_group 0;" ::: "memory");
        __syncthreads();

        if (c + 2 < nch) {
            int nb = buf + 2; if (nb >= 3) nb -= 3;
            const uint32_t b = su + nb * STAGE;
            const size_t k0 = (size_t)(c + 2) << 5;
            cpa16(b + dA,       Ah + gA  + k0);
            cpa16(b + PA + dB0, Bh + gB0 + k0);
            cpa16(b + PA + dB1, Bh + gB1 + k0);
            cp_commit();
        }

        const uint32_t bb = su + buf * STAGE;
        #pragma unroll
        for (int ks = 0; ks < 2; ks++) {
            uint32_t a[4][4], bH[4][2];
            #pragma unroll
            for (int i = 0; i < 4; i++)
                ldm4(a[i], bb + (uint32_t)((wm + i * 16 + arow) * 80 + ks * 32 + acol));
            #pragma unroll
            for (int p = 0; p < 2; p++) {
                uint32_t r[4];
                ldm4(r, bb + PA + (uint32_t)((wn + p * 16) * 80 + ks * 32) + boff);
                bH[p*2+0][0] = r[0]; bH[p*2+0][1] = r[1];
                bH[p*2+1][0] = r[2]; bH[p*2+1][1] = r[3];
            }
            #pragma unroll
            for (int i = 0; i < 4; i++)
                #pragma unroll
                for (int j = 0; j < 4; j++) mma16816(acc[i][j], a[i], bH[j]);
        }
        if (++buf == 3) buf = 0;
    }

    // -------- epilogue --------
    #pragma unroll
    for (int i = 0; i < 4; i++) {
        #pragma unroll
        for (int j = 0; j < 4; j++) {
            const int r0 = bm + wm + i * 16 + (lane >> 2);
            const int r1 = r0 + 8;
            const int cc = bn + wn + j * 8 + (lane & 3) * 2;
            float v[4] = {acc[i][j][0], acc[i][j][1], acc[i][j][2], acc[i][j][3]};

            if constexpr (EPI == 0) {
                v[0] *= alpha; v[1] *= alpha; v[2] *= alpha; v[3] *= alpha;
            }
            if constexpr (EPI == 3 || EPI == 4) {
                const float2 bbv = *reinterpret_cast<const float2*>(bias + cc);
                v[0] += bbv.x; v[1] += bbv.y; v[2] += bbv.x; v[3] += bbv.y;
            }
            if constexpr (EPI == 3) {
                v[0] = gelu_exact(v[0]); v[1] = gelu_exact(v[1]);
                v[2] = gelu_exact(v[2]); v[3] = gelu_exact(v[3]);
            }
            if constexpr (EPI == 2 || EPI == 4) {
                const float* rp = res + (size_t)strRes * bz;
                const float2 q0 = *reinterpret_cast<const float2*>(rp + (size_t)r0 * ldc + cc);
                const float2 q1 = *reinterpret_cast<const float2*>(rp + (size_t)r1 * ldc + cc);
                v[0] += q0.x; v[1] += q0.y; v[2] += q1.x; v[3] += q1.y;
            }

            if constexpr (EPI == 0 || EPI == 2 || EPI == 4) {
                float* cp0 = Cf + (size_t)strC * bz + (size_t)r0 * ldc + cc;
                float* cp1 = Cf + (size_t)strC * bz + (size_t)r1 * ldc + cc;
                *reinterpret_cast<float2*>(cp0) = make_float2(v[0], v[1]);
                *reinterpret_cast<float2*>(cp1) = make_float2(v[2], v[3]);
            } else {  // EPI 3, 5: fp16 out
                *reinterpret_cast<f162*>(Ch + (size_t)strC * bz + (size_t)r0 * ldc + cc) =
                    __halves2half2(__float2half_rn(v[0]), __float2half_rn(v[1]));
                *reinterpret_cast<f162*>(Ch + (size_t)strC * bz + (size_t)r1 * ldc + cc) =
                    __halves2half2(__float2half_rn(v[2]), __float2half_rn(v[3]));
            }
        }
    }
}

// ---------------- LayerNorm -> fp16 ----------------
__global__ void __launch_bounds__(256) ln_hi_kernel(
    const float* __restrict__ x, const float* __restrict__ g,
    const float* __restrict__ b, f16* __restrict__ yh)
{
    const size_t row = blockIdx.x;
    const float4 v = reinterpret_cast<const float4*>(x + row * HDIM)[threadIdx.x];
    float s  = v.x + v.y + v.z + v.w;
    float ss = v.x * v.x + v.y * v.y + v.z * v.z + v.w * v.w;

    __shared__ float sm_s[8], sm_ss[8];
    #pragma unroll
    for (int o = 16; o; o >>= 1) {
        s  += __shfl_xor_sync(0xffffffffu, s,  o);
        ss += __shfl_xor_sync(0xffffffffu, ss, o);
    }
    if ((threadIdx.x & 31) == 0) { sm_s[threadIdx.x >> 5] = s; sm_ss[threadIdx.x >> 5] = ss; }
    __syncthreads();
    if (threadIdx.x < 32) {
        float ws  = (threadIdx.x < 8) ? sm_s [threadIdx.x] : 0.0f;
        float wss = (threadIdx.x < 8) ? sm_ss[threadIdx.x] : 0.0f;
        #pragma unroll
        for (int o = 4; o; o >>= 1) {
            ws  += __shfl_xor_sync(0xffffffffu, ws,  o);
            wss += __shfl_xor_sync(0xffffffffu, wss, o);
        }
        if (threadIdx.x == 0) { sm_s[0] = ws; sm_ss[0] = wss; }
    }
    __syncthreads();

    const float mu  = sm_s[0]  * (1.0f / HDIM);
    const float var = sm_ss[0] * (1.0f / HDIM) - mu * mu;
    const float rs  = rsqrtf(var + 1e-5f);

    const float4 gv = reinterpret_cast<const float4*>(g)[threadIdx.x];
    const float4 bv = reinterpret_cast<const float4*>(b)[threadIdx.x];
    const size_t off = row * HDIM + (size_t)threadIdx.x * 4;
    *reinterpret_cast<f162*>(yh + off) = __halves2half2(
        __float2half_rn((v.x - mu) * rs * gv.x + bv.x),
        __float2half_rn((v.y - mu) * rs * gv.y + bv.y));
    *reinterpret_cast<f162*>(yh + off + 2) = __halves2half2(
        __float2half_rn((v.z - mu) * rs * gv.z + bv.z),
        __float2half_rn((v.w - mu) * rs * gv.w + bv.w));
}

// ---------------- Softmax (2048) fp32 -> fp16 ----------------
__global__ void __launch_bounds__(256) softmax_hi_kernel(
    const float* __restrict__ s, f16* __restrict__ ph)
{
    const size_t row = blockIdx.x;
    const float4* r = reinterpret_cast<const float4*>(s) + row * (NSEQ / 4);
    const int t = threadIdx.x;
    const float4 a = r[t];
    const float4 c = r[t + 256];
    float vals[8] = {a.x, a.y, a.z, a.w, c.x, c.y, c.z, c.w};

    __shared__ float sm[8];
    float m = vals[0];
    #pragma unroll
    for (int i = 1; i < 8; i++) m = fmaxf(m, vals[i]);
    #pragma unroll
    for (int o = 16; o; o >>= 1) m = fmaxf(m, __shfl_xor_sync(0xffffffffu, m, o));
    if ((t & 31) == 0) sm[t >> 5] = m;
    __syncthreads();
    if (t < 32) {
        float w = (t < 8) ? sm[t] : -INFINITY;
        #pragma unroll
        for (int o = 4; o; o >>= 1) w = fmaxf(w, __shfl_xor_sync(0xffffffffu, w, o));
        if (t == 0) sm[0] = w;
    }
    __syncthreads();
    m = sm[0];
    __syncthreads();

    float sum = 0.0f;
    #pragma unroll
    for (int i = 0; i < 8; i++) { vals[i] = expf(vals[i] - m); sum += vals[i]; }
    #pragma unroll
    for (int o = 16; o; o >>= 1) sum += __shfl_xor_sync(0xffffffffu, sum, o);
    if ((t & 31) == 0) sm[t >> 5] = sum;
    __syncthreads();
    if (t < 32) {
        float w = (t < 8) ? sm[t] : 0.0f;
        #pragma unroll
        for (int o = 4; o; o >>= 1) w += __shfl_xor_sync(0xffffffffu, w, o);
        if (t == 0) sm[0] = w;
    }
    __syncthreads();
    const float inv = 1.0f / sm[0];

    const size_t base = row * NSEQ;
    #pragma unroll
    for (int half = 0; half < 2; half++) {
        const size_t off = base + (size_t)(t + half * 256) * 4;
        const int v0 = half * 4;
        *reinterpret_cast<f162*>(ph + off) = __halves2half2(
            __float2half_rn(vals[v0 + 0] * inv), __float2half_rn(vals[v0 + 1] * inv));
        *reinterpret_cast<f162*>(ph + off + 2) = __halves2half2(
            __float2half_rn(vals[v0 + 2] * inv), __float2half_rn(vals[v0 + 3] * inv));
    }
}

// ---------------- fp32 W[R,C] -> fp16 W^T[C,R] ----------------
__global__ void __launch_bounds__(256) wcast_t_kernel(
    const float* __restrict__ W, int R, int C, f16* __restrict__ Th)
{
    __shared__ float t[32][33];
    const int bx = blockIdx.x * 32;   // C
    const int by = blockIdx.y * 32;   // R
    const int tx = threadIdx.x, ty = threadIdx.y;
    #pragma unroll
    for (int i = 0; i < 4; i++)
        t[ty + i * 8][tx] = W[(size_t)(by + ty + i * 8) * C + bx + tx];
    __syncthreads();
    #pragma unroll
    for (int i = 0; i < 4; i++)
        Th[(size_t)(bx + ty + i * 8) * R + by + tx] = __float2half_rn(t[tx][ty + i * 8]);
}

// ---------------- V [B][NSEQ,H] -> Vt [B][H,NSEQ] ----------------
__global__ void __launch_bounds__(256) vtrans_kernel(
    const f16* __restrict__ vh, f16* __restrict__ vth)
{
    const int b = blockIdx.z;
    const f16* src = vh + (size_t)b * NSEQ * HDIM;
    f16* dst       = vth + (size_t)b * HDIM * NSEQ;

    __shared__ f16 t[32][33];
    const int bx = blockIdx.x * 32;   // H
    const int by = blockIdx.y * 32;   // NSEQ
    const int tx = threadIdx.x, ty = threadIdx.y;
    #pragma unroll
    for (int i = 0; i < 4; i++)
        t[ty + i * 8][tx] = src[(size_t)(by + ty + i * 8) * HDIM + bx + tx];
    __syncthreads();
    #pragma unroll
    for (int i = 0; i < 4; i++)
        dst[(size_t)(bx + ty + i * 8) * NSEQ + by + tx] = t[tx][ty + i * 8];
}

// ---------------------------------------------------------------------------
// kernel_launch — inputs: 0:x 1:ln1_g 2:ln1_b 3:Wq 4:Wk 5:Wv 6:ln2_g 7:ln2_b
//                         8:W1 9:b1 10:W2 11:b2
// ---------------------------------------------------------------------------
extern "C" void kernel_launch(void* const* d_in, const int*, int,
                              void* d_out, int)
{
    const float* x     = (const float*)d_in[0];
    const float* ln1_g = (const float*)d_in[1];
    const float* ln1_b = (const float*)d_in[2];
    const float* Wq    = (const float*)d_in[3];
    const float* Wk    = (const float*)d_in[4];
    const float* Wv    = (const float*)d_in[5];
    const float* ln2_g = (const float*)d_in[6];
    const float* ln2_b = (const float*)d_in[7];
    const float* W1    = (const float*)d_in[8];
    const float* b1    = (const float*)d_in[9];
    const float* W2    = (const float*)d_in[10];
    const float* b2    = (const float*)d_in[11];
    float* out = (float*)d_out;

    f16 *lnh, *qh, *kh, *vh, *vth, *ph, *hh, *wqh, *wkh, *wvh, *w1h, *w2h;
    float *s, *x1;
    cudaGetSymbolAddress((void**)&lnh, g_lnh);
    cudaGetSymbolAddress((void**)&qh, g_qh);
    cudaGetSymbolAddress((void**)&kh, g_kh);
    cudaGetSymbolAddress((void**)&vh, g_vh);
    cudaGetSymbolAddress((void**)&vth, g_vth);
    cudaGetSymbolAddress((void**)&ph, g_ph);
    cudaGetSymbolAddress((void**)&hh, g_hh);
    cudaGetSymbolAddress((void**)&wqh, g_wqh);
    cudaGetSymbolAddress((void**)&wkh, g_wkh);
    cudaGetSymbolAddress((void**)&wvh, g_wvh);
    cudaGetSymbolAddress((void**)&w1h, g_w1h);
    cudaGetSymbolAddress((void**)&w2h, g_w2h);
    cudaGetSymbolAddress((void**)&s, g_s);
    cudaGetSymbolAddress((void**)&x1, g_x1);

    cudaFuncSetAttribute(mm_kernel<0>, cudaFuncAttributeMaxDynamicSharedMemorySize, MM_SMEM);
    cudaFuncSetAttribute(mm_kernel<2>, cudaFuncAttributeMaxDynamicSharedMemorySize, MM_SMEM);
    cudaFuncSetAttribute(mm_kernel<3>, cudaFuncAttributeMaxDynamicSharedMemorySize, MM_SMEM);
    cudaFuncSetAttribute(mm_kernel<4>, cudaFuncAttributeMaxDynamicSharedMemorySize, MM_SMEM);
    cudaFuncSetAttribute(mm_kernel<5>, cudaFuncAttributeMaxDynamicSharedMemorySize, MM_SMEM);

    const long long sNH = (long long)NSEQ * HDIM;
    const long long sNN = (long long)NSEQ * NSEQ;
    dim3 wb(32, 8);

    // LN1 + weight casts
    ln_hi_kernel<<<MTOT, 256>>>(x, ln1_g, ln1_b, lnh);
    wcast_t_kernel<<<dim3(HDIM/32, HDIM/32), wb>>>(Wq, HDIM, HDIM, wqh);
    wcast_t_kernel<<<dim3(HDIM/32, HDIM/32), wb>>>(Wk, HDIM, HDIM, wkh);
    wcast_t_kernel<<<dim3(HDIM/32, HDIM/32), wb>>>(Wv, HDIM, HDIM, wvh);

    // QKV (M=16384, N=1024, K=1024)
    { dim3 g(HDIM/256, MTOT/128);
      mm_kernel<5><<<g, 512, MM_SMEM>>>(lnh, wqh, HDIM, 0, 0, 0, HDIM,
                                        1.0f, nullptr, nullptr, nullptr, 0, qh);
      mm_kernel<5><<<g, 512, MM_SMEM>>>(lnh, wkh, HDIM, 0, 0, 0, HDIM,
                                        1.0f, nullptr, nullptr, nullptr, 0, kh);
      mm_kernel<5><<<g, 512, MM_SMEM>>>(lnh, wvh, HDIM, 0, 0, 0, HDIM,
                                        1.0f, nullptr, nullptr, nullptr, 0, vh); }

    // scores = (Q @ K^T)/32, fp32
    { dim3 g(NSEQ/256, NSEQ/128, BATCH);
      mm_kernel<0><<<g, 512, MM_SMEM>>>(qh, kh, HDIM, sNH, sNH, sNN, NSEQ,
                                        0.03125f, s, nullptr, nullptr, 0, nullptr); }

    // softmax -> probs fp16
    softmax_hi_kernel<<<BATCH * NSEQ, 256>>>(s, ph);

    // V^T per batch
    vtrans_kernel<<<dim3(HDIM/32, NSEQ/32, BATCH), dim3(32, 8)>>>(vh, vth);

    // x1 = x + P @ V
    { dim3 g(HDIM/256, NSEQ/128, BATCH);
      mm_kernel<2><<<g, 512, MM_SMEM>>>(ph, vth, NSEQ, sNN, sNH, sNH, HDIM,
                                        1.0f, x1, nullptr, x, sNH, nullptr); }

    // LN2
    ln_hi_kernel<<<MTOT, 256>>>(x1, ln2_g, ln2_b, lnh);

    // h = gelu(ln @ W1 + b1)
    wcast_t_kernel<<<dim3(FDIM/32, HDIM/32), wb>>>(W1, HDIM, FDIM, w1h);
    { dim3 g(FDIM/256, MTOT/128);
      mm_kernel<3><<<g, 512, MM_SMEM>>>(lnh, w1h, HDIM, 0, 0, 0, FDIM,
                                        1.0f, nullptr, b1, nullptr, 0, hh); }

    // out = x1 + h @ W2 + b2
    wcast_t_kernel<<<dim3(HDIM/32, FDIM/32), wb>>>(W2, FDIM, HDIM, w2h);
    { dim3 g(HDIM/256, MTOT/128);
      mm_kernel<4><<<g, 512, MM_SMEM>>>(hh, w2h, FDIM, 0, 0, 0, HDIM,
                                        1.0f, out, b2, x1, 0, nullptr); }
}